// round 5
// baseline (speedup 1.0000x reference)
#include <cuda_runtime.h>
#include <cstddef>

typedef unsigned long long ull;
typedef unsigned int uint;

// ---------------- problem constants (shapes fixed by the dataset) -----------
#define MAXN 100000
#define MAXE 1600000
#define MAXET (MAXE + MAXN)
#define FN   128     // node feature dim (layer1 input)
#define FE   32      // edge feature dim
#define HID  64

// ---------------- device scratch (static: no allocation allowed) ------------
__device__ float g_loop[MAXN * FE];        // self-loop edge attr (mean of incoming)
__device__ float g_xl  [MAXN * HID];       // source-side transform
__device__ float g_xr  [MAXN * HID];       // target-side transform
__device__ float g_exc [MAXET];            // exp(logit), ORIGINAL edge-id order
__device__ float g_out [MAXN * HID];       // layer output
__device__ int   g_deg [MAXN];
__device__ int   g_rowptr[MAXN + 1];
__device__ int   g_cur [MAXN];
__device__ int   g_bsum[128];
__device__ int2  g_csr_se [MAXET];         // (src, eid) packed, grouped by dst

// ---------------- small helpers ---------------------------------------------
__device__ __forceinline__ uint to_tf32(float f) {
    uint r; asm("cvt.rna.tf32.f32 %0, %1;" : "=r"(r) : "f"(f)); return r;
}
__device__ __forceinline__ void tf32_split(float v, uint& hb, uint& lb) {
    asm("cvt.rna.tf32.f32 %0, %1;" : "=r"(hb) : "f"(v));
    float hf = __uint_as_float(hb);
    asm("cvt.rna.tf32.f32 %0, %1;" : "=r"(lb) : "f"(v - hf));
}
__device__ __forceinline__ void mma_tf32(float acc[4], const uint a[4], uint b0, uint b1) {
    asm volatile(
        "mma.sync.aligned.m16n8k8.row.col.f32.tf32.tf32.f32 "
        "{%0,%1,%2,%3}, {%4,%5,%6,%7}, {%8,%9}, {%0,%1,%2,%3};"
        : "+f"(acc[0]), "+f"(acc[1]), "+f"(acc[2]), "+f"(acc[3])
        : "r"(a[0]), "r"(a[1]), "r"(a[2]), "r"(a[3]), "r"(b0), "r"(b1));
}
__device__ __forceinline__ void redv4(float* p, float4 u) {
    asm volatile("red.global.add.v4.f32 [%0], {%1,%2,%3,%4};"
                 :: "l"(p), "f"(u.x), "f"(u.y), "f"(u.z), "f"(u.w) : "memory");
}

// ================= CSR build + self-loop accumulation ========================
__global__ void zero_kernel(int N) {
    int t = blockIdx.x * blockDim.x + threadIdx.x;
    if (t < N) g_deg[t] = 0;
    float4* l4 = reinterpret_cast<float4*>(g_loop);
    const float4 z = make_float4(0.f, 0.f, 0.f, 0.f);
    int total = N * 8;
    for (int k = t; k < total; k += gridDim.x * blockDim.x) l4[k] = z;
}

// degree count + self-loop attr accumulation (sequential ea reads)
__global__ void deg_kernel(const int* __restrict__ ei, const float* __restrict__ ea,
                           int E, int Etot) {
    int i = blockIdx.x * blockDim.x + threadIdx.x;
    if (i >= Etot) return;
    int d = (i < E) ? ei[E + i] : (i - E);
    atomicAdd(&g_deg[d], 1);
    if (i < E) {
        const float4* ea4 = reinterpret_cast<const float4*>(ea) + (size_t)i * 8;
        float* base = g_loop + (size_t)d * FE;
        #pragma unroll
        for (int q = 0; q < 8; ++q) redv4(base + 4 * q, ea4[q]);
    }
}

// divide accumulated loop attr by real in-degree (deg-1; every node has 1 self loop)
__global__ void div_kernel(int N) {
    int t = blockIdx.x * blockDim.x + threadIdx.x;
    int total = N * 8;
    if (t >= total) return;
    int n = t >> 3;
    float inv = 1.f / (float)max(g_deg[n] - 1, 1);
    float4* l4 = reinterpret_cast<float4*>(g_loop);
    float4 v = l4[t];
    v.x *= inv; v.y *= inv; v.z *= inv; v.w *= inv;
    l4[t] = v;
}

// grid scan stage A: per-block exclusive scan + block sums
__global__ __launch_bounds__(1024) void scanA_kernel(int N) {
    __shared__ int wsum[32];
    const int i = blockIdx.x * 1024 + threadIdx.x;
    const int lane = threadIdx.x & 31, wid = threadIdx.x >> 5;
    int v = (i < N) ? g_deg[i] : 0;
    int s = v;
    #pragma unroll
    for (int off = 1; off < 32; off <<= 1) {
        int t = __shfl_up_sync(0xffffffffu, s, off);
        if (lane >= off) s += t;
    }
    if (lane == 31) wsum[wid] = s;
    __syncthreads();
    if (wid == 0) {
        int ws = wsum[lane];
        #pragma unroll
        for (int off = 1; off < 32; off <<= 1) {
            int t = __shfl_up_sync(0xffffffffu, ws, off);
            if (lane >= off) ws += t;
        }
        wsum[lane] = ws;
    }
    __syncthreads();
    int excl = s - v + (wid ? wsum[wid - 1] : 0);
    if (i < N) g_rowptr[i] = excl;
    if (threadIdx.x == 1023) g_bsum[blockIdx.x] = excl + v;
}

// stage B: exclusive scan of block sums (single block, nb <= 128)
__global__ void scanB_kernel(int nb) {
    __shared__ int sh[128];
    const int t = threadIdx.x;
    int v = (t < nb) ? g_bsum[t] : 0;
    sh[t] = v;
    __syncthreads();
    for (int off = 1; off < 128; off <<= 1) {
        int x = (t >= off) ? sh[t - off] : 0;
        __syncthreads();
        sh[t] += x;
        __syncthreads();
    }
    g_bsum[t] = sh[t] - v;
}

// stage C: add block offsets, init cursors
__global__ __launch_bounds__(1024) void scanC_kernel(int N, int Etot) {
    int i = blockIdx.x * 1024 + threadIdx.x;
    if (i < N) {
        int rp = g_rowptr[i] + g_bsum[blockIdx.x];
        g_rowptr[i] = rp;
        g_cur[i]    = rp;
    }
    if (i == 0) g_rowptr[N] = Etot;
}

__global__ void scatter_kernel(const int* __restrict__ ei, int E, int Etot) {
    int i = blockIdx.x * blockDim.x + threadIdx.x;
    if (i >= Etot) return;
    int s, d;
    if (i < E) { s = ei[i]; d = ei[E + i]; }
    else       { s = d = i - E; }
    int pos = atomicAdd(&g_cur[d], 1);
    g_csr_se[pos] = make_int2(s, i);
}

// ---------------- node linear transforms via 3xTF32 tensor MMA ---------------
template<int IN, bool FROM_OUT>
__global__ __launch_bounds__(256) void lin_mma_kernel(
        const float* __restrict__ inp,
        const float* __restrict__ Wl, const float* __restrict__ bl,
        const float* __restrict__ Wr, const float* __restrict__ br,
        const float* __restrict__ prevBias, int N) {
    constexpr int KC = 16;
    __shared__ uint XsH[64][20], XsL[64][20];
    __shared__ uint WsH[KC][132], WsL[KC][132];

    const int t = threadIdx.x;
    const int nb = blockIdx.x * 64;
    const int lane = t & 31;
    const int w = t >> 5;
    const int mt = w & 3;
    const int half = w >> 2;
    const int g = lane >> 2, c = lane & 3;

    float acc[8][4];
    #pragma unroll
    for (int nt = 0; nt < 8; ++nt) {
        acc[nt][0] = acc[nt][1] = acc[nt][2] = acc[nt][3] = 0.f;
    }

    for (int kc = 0; kc < IN; kc += KC) {
        __syncthreads();
        for (int idx = t; idx < 64 * KC; idx += 256) {
            int row = idx / KC, col = idx - row * KC;
            int node = nb + row;
            float v = 0.f;
            if (node < N) {
                int j = kc + col;
                if (FROM_OUT) v = fmaxf(g_out[(size_t)node * HID + j] + prevBias[j], 0.f);
                else          v = inp[(size_t)node * IN + j];
            }
            uint hb, lb; tf32_split(v, hb, lb);
            XsH[row][col] = hb; XsL[row][col] = lb;
        }
        for (int idx = t; idx < KC * 128; idx += 256) {
            int row = idx >> 7, col = idx & 127;
            int k = kc + row;
            float v = (col < HID) ? Wl[k * HID + col] : Wr[k * HID + (col - HID)];
            uint hb, lb; tf32_split(v, hb, lb);
            WsH[row][col] = hb; WsL[row][col] = lb;
        }
        __syncthreads();
        #pragma unroll
        for (int kk = 0; kk < KC; kk += 8) {
            uint aH[4], aL[4];
            aH[0] = XsH[mt * 16 + g    ][kk + c];
            aH[1] = XsH[mt * 16 + g + 8][kk + c];
            aH[2] = XsH[mt * 16 + g    ][kk + c + 4];
            aH[3] = XsH[mt * 16 + g + 8][kk + c + 4];
            aL[0] = XsL[mt * 16 + g    ][kk + c];
            aL[1] = XsL[mt * 16 + g + 8][kk + c];
            aL[2] = XsL[mt * 16 + g    ][kk + c + 4];
            aL[3] = XsL[mt * 16 + g + 8][kk + c + 4];
            #pragma unroll
            for (int nt = 0; nt < 8; ++nt) {
                int col = half * 64 + nt * 8 + g;
                uint bH0 = WsH[kk + c    ][col];
                uint bH1 = WsH[kk + c + 4][col];
                uint bL0 = WsL[kk + c    ][col];
                uint bL1 = WsL[kk + c + 4][col];
                mma_tf32(acc[nt], aH, bH0, bH1);
                mma_tf32(acc[nt], aL, bH0, bH1);
                mma_tf32(acc[nt], aH, bL0, bL1);
            }
        }
    }

    const float* bias = half ? br : bl;
    float2* dst2 = reinterpret_cast<float2*>(half ? g_xr : g_xl);
    const int m0 = nb + mt * 16 + g;
    const int m1 = m0 + 8;
    #pragma unroll
    for (int nt = 0; nt < 8; ++nt) {
        int colL = nt * 8 + 2 * c;
        float bx = bias[colL], by = bias[colL + 1];
        if (m0 < N) dst2[(size_t)m0 * 32 + nt * 4 + c] = make_float2(acc[nt][0] + bx, acc[nt][1] + by);
        if (m1 < N) dst2[(size_t)m1 * 32 + nt * 4 + c] = make_float2(acc[nt][2] + bx, acc[nt][3] + by);
    }
}

// ---------------- edge pass A: tensor-core e-GEMM + logits (ORIGINAL order) --
__global__ __launch_bounds__(256) void edgeA_kernel(
        const int* __restrict__ ei, const float* __restrict__ ea,
        const float* __restrict__ We, const float* __restrict__ att,
        int E, int N) {
    __shared__ uint Wes[32 * 68];            // tf32-converted We, padded rows

    const int t = threadIdx.x;
    for (int idx = t; idx < 32 * 64; idx += 256) {
        int row = idx >> 6, col = idx & 63;
        Wes[row * 68 + col] = to_tf32(We[idx]);
    }
    __syncthreads();

    const int lane = t & 31;
    const int w = t >> 5;
    const int g = lane >> 2;                 // row group 0..7
    const int c = lane & 3;                  // col-in-group 0..3
    const int Etot = E + N;
    const int nTiles = (Etot + 15) >> 4;
    const int gw = blockIdx.x * 8 + w;
    const int gws = gridDim.x * 8;

    const float2* xl2 = reinterpret_cast<const float2*>(g_xl);
    const float2* xr2 = reinterpret_cast<const float2*>(g_xr);
    const float2* att2 = reinterpret_cast<const float2*>(att);

    for (int tile = gw; tile < nTiles; tile += gws) {
        const int i0 = tile << 4;
        const int rowA = i0 + g;             // edge id for this lane's rows
        const int rowB = i0 + g + 8;

        int sA = 0, dA = 0, sB = 0, dB = 0;
        const float *pA = ea, *pB = ea;
        if (rowA < E)         { sA = ei[rowA]; dA = ei[E + rowA]; pA = ea + (size_t)rowA * FE; }
        else if (rowA < Etot) { sA = dA = rowA - E; pA = g_loop + (size_t)sA * FE; }
        if (rowB < E)         { sB = ei[rowB]; dB = ei[E + rowB]; pB = ea + (size_t)rowB * FE; }
        else if (rowB < Etot) { sB = dB = rowB - E; pB = g_loop + (size_t)sB * FE; }

        uint afr[4][4];
        #pragma unroll
        for (int ks = 0; ks < 4; ++ks) {
            afr[ks][0] = to_tf32(pA[ks * 8 + c]);
            afr[ks][1] = to_tf32(pB[ks * 8 + c]);
            afr[ks][2] = to_tf32(pA[ks * 8 + c + 4]);
            afr[ks][3] = to_tf32(pB[ks * 8 + c + 4]);
        }

        float partA = 0.f, partB = 0.f;
        #pragma unroll
        for (int nt = 0; nt < 8; ++nt) {
            float acc[4] = {0.f, 0.f, 0.f, 0.f};
            #pragma unroll
            for (int ks = 0; ks < 4; ++ks) {
                uint b0 = Wes[(ks * 8 + c)     * 68 + nt * 8 + g];
                uint b1 = Wes[(ks * 8 + c + 4) * 68 + nt * 8 + g];
                mma_tf32(acc, afr[ks], b0, b1);
            }
            float2 xlA = xl2[(size_t)sA * 32 + nt * 4 + c];
            float2 xrA = xr2[(size_t)dA * 32 + nt * 4 + c];
            float2 xlB = xl2[(size_t)sB * 32 + nt * 4 + c];
            float2 xrB = xr2[(size_t)dB * 32 + nt * 4 + c];
            float u0 = acc[0] + xlA.x + xrA.x;
            float u1 = acc[1] + xlA.y + xrA.y;
            float u2 = acc[2] + xlB.x + xrB.x;
            float u3 = acc[3] + xlB.y + xrB.y;
            u0 = fmaxf(u0, 0.f) + 0.2f * fminf(u0, 0.f);
            u1 = fmaxf(u1, 0.f) + 0.2f * fminf(u1, 0.f);
            u2 = fmaxf(u2, 0.f) + 0.2f * fminf(u2, 0.f);
            u3 = fmaxf(u3, 0.f) + 0.2f * fminf(u3, 0.f);
            float2 av = att2[nt * 4 + c];
            partA = fmaf(u0, av.x, fmaf(u1, av.y, partA));
            partB = fmaf(u2, av.x, fmaf(u3, av.y, partB));
        }
        partA += __shfl_xor_sync(0xffffffffu, partA, 1);
        partA += __shfl_xor_sync(0xffffffffu, partA, 2);
        partB += __shfl_xor_sync(0xffffffffu, partB, 1);
        partB += __shfl_xor_sync(0xffffffffu, partB, 2);
        if (c == 0) {
            if (rowA < Etot) g_exc[rowA] = __expf(partA);
            if (rowB < Etot) g_exc[rowB] = __expf(partB);
        }
    }
}

// ---------------- edge pass B: per-dst softmax-normalize + aggregate ---------
__global__ __launch_bounds__(256) void edgeB_kernel(int N) {
    const int lane = threadIdx.x & 31;
    const int d = blockIdx.x * 8 + (threadIdx.x >> 5);
    if (d >= N) return;
    const int rp0 = g_rowptr[d], rp1 = g_rowptr[d + 1];

    // denominator: g_exc gathered via eid (L2-resident)
    float den = 0.f;
    for (int e = rp0 + lane; e < rp1; e += 32) den += g_exc[g_csr_se[e].y];
    #pragma unroll
    for (int off = 16; off > 0; off >>= 1)
        den += __shfl_xor_sync(0xffffffffu, den, off);
    const float inv = 1.f / den;

    const float2* xl2 = reinterpret_cast<const float2*>(g_xl);
    float ax = 0.f, ay = 0.f;
    if (rp0 < rp1) {
        int2 se = g_csr_se[rp0];
        int src = se.x;
        float wgt = g_exc[se.y];
        for (int e = rp0 + 1; e <= rp1; ++e) {
            int nsrc = 0; float nw = 0.f;
            if (e < rp1) { int2 n = g_csr_se[e]; nsrc = n.x; nw = g_exc[n.y]; }
            float2 xv = xl2[(size_t)src * 32 + lane];
            ax = fmaf(wgt, xv.x, ax);
            ay = fmaf(wgt, xv.y, ay);
            src = nsrc; wgt = nw;
        }
    }
    float2* out2 = reinterpret_cast<float2*>(g_out);
    out2[(size_t)d * 32 + lane] = make_float2(ax * inv, ay * inv);
}

// ---------------- kernel: final MLP at node_idx ------------------------------
__global__ void fin_kernel(const int* __restrict__ idx, const float* __restrict__ bias2,
                           const float* __restrict__ y,
                           const float* __restrict__ W0, const float* __restrict__ b0,
                           const float* __restrict__ W1, const float* __restrict__ b1,
                           const float* __restrict__ W2, const float* __restrict__ b2,
                           float* __restrict__ dout, int M, int rf) {
    __shared__ float sh[4][64];
    __shared__ float sz[4][32];
    const int w = threadIdx.x >> 5, lane = threadIdx.x & 31;
    const int m = blockIdx.x * 4 + w;
    if (m >= M) return;
    const int v = idx[m];

    float h0 = fmaxf(g_out[(size_t)v * HID + lane]      + bias2[lane],      0.f);
    float h1 = fmaxf(g_out[(size_t)v * HID + 32 + lane] + bias2[32 + lane], 0.f);
    sh[w][lane] = h0; sh[w][32 + lane] = h1;
    __syncwarp();

    int k = v / rf;
    float y0 = y[2 * k], y1 = y[2 * k + 1];
    float q0 = fmaxf(y0 * W0[0] + y1 * W0[2] + b0[0], 0.f);
    float q1 = fmaxf(y0 * W0[1] + y1 * W0[3] + b0[1], 0.f);

    float z = b1[lane];
    #pragma unroll
    for (int j = 0; j < 64; ++j) z += sh[w][j] * W1[j * 32 + lane];
    z += q0 * W1[64 * 32 + lane] + q1 * W1[65 * 32 + lane];
    z = fmaxf(z, 0.f);
    sz[w][lane] = z;
    __syncwarp();

    float o = b2[lane];
    #pragma unroll
    for (int j = 0; j < 32; ++j) o += sz[w][j] * W2[j * 32 + lane];
    dout[m * 32 + lane] = o;
}

// ---------------- launch ------------------------------------------------------
extern "C" void kernel_launch(void* const* d_in, const int* in_sizes, int n_in,
                              void* d_out, int out_size) {
    const float* x    = (const float*)d_in[0];
    const float* ea   = (const float*)d_in[1];
    const float* y    = (const float*)d_in[2];
    const float* Wl1  = (const float*)d_in[3];
    const float* bl1  = (const float*)d_in[4];
    const float* Wr1  = (const float*)d_in[5];
    const float* br1  = (const float*)d_in[6];
    const float* We1  = (const float*)d_in[7];
    const float* att1 = (const float*)d_in[8];
    const float* bias1= (const float*)d_in[9];
    const float* Wl2  = (const float*)d_in[10];
    const float* bl2  = (const float*)d_in[11];
    const float* Wr2  = (const float*)d_in[12];
    const float* br2  = (const float*)d_in[13];
    const float* We2  = (const float*)d_in[14];
    const float* att2 = (const float*)d_in[15];
    const float* bias2= (const float*)d_in[16];
    const float* W0   = (const float*)d_in[17];
    const float* b0   = (const float*)d_in[18];
    const float* W1   = (const float*)d_in[19];
    const float* b1   = (const float*)d_in[20];
    const float* W2   = (const float*)d_in[21];
    const float* b2   = (const float*)d_in[22];
    const int*   ei   = (const int*)  d_in[23];
    const int*   nidx = (const int*)  d_in[24];

    const int N    = in_sizes[0] / FN;
    const int E    = in_sizes[23] / 2;
    const int Etot = E + N;
    const int M    = in_sizes[24];
    const int NG   = in_sizes[2] / 2;
    const int rf   = N / NG;

    const int EBLK = (Etot + 255) / 256;
    const int NWRP = (N + 7) / 8;        // warp-per-node kernels
    const int NB1K = (N + 1023) / 1024;  // 1024-thread node kernels

    // ---- CSR build + self-loop mean ----
    zero_kernel    <<<2048, 256>>>(N);
    deg_kernel     <<<EBLK, 256>>>(ei, ea, E, Etot);
    scanA_kernel   <<<NB1K, 1024>>>(N);
    scanB_kernel   <<<1, 128>>>(NB1K);
    scanC_kernel   <<<NB1K, 1024>>>(N, Etot);
    scatter_kernel <<<EBLK, 256>>>(ei, E, Etot);
    div_kernel     <<<(N * 8 + 255) / 256, 256>>>(N);

    // ---- layer 1 ----
    lin_mma_kernel<FN, false><<<(N + 63) / 64, 256>>>(x, Wl1, bl1, Wr1, br1, nullptr, N);
    edgeA_kernel<<<2048, 256>>>(ei, ea, We1, att1, E, N);
    edgeB_kernel<<<NWRP, 256>>>(N);

    // ---- layer 2 ----
    lin_mma_kernel<HID, true><<<(N + 63) / 64, 256>>>(x, Wl2, bl2, Wr2, br2, bias1, N);
    edgeA_kernel<<<2048, 256>>>(ei, ea, We2, att2, E, N);
    edgeB_kernel<<<NWRP, 256>>>(N);

    // ---- final MLP at node_idx ----
    fin_kernel<<<(M + 3) / 4, 128>>>(nidx, bias2, y, W0, b0, W1, b1, W2, b2,
                                     (float*)d_out, M, rf);
}